// round 4
// baseline (speedup 1.0000x reference)
#include <cuda_runtime.h>
#include <cuda_bf16.h>
#include <stdint.h>
#include <math.h>

#define SDIM 2048
#define DDIM 64
#define TQ 16
#define NTHREADS 512
#define CHUNK 128
#define KSTR  72       // K staging row stride (uint16): 36 words ≡ 4 mod 32 -> conflict-free
#define VSTR  136      // V^T staging row stride (uint16): 68 words ≡ 4 mod 32 -> conflict-free
#define KBUF  9216     // uint16 per K sub-array (128*72)
#define VBUF  8704     // uint16 per V sub-array (64*136)

// smem byte layout
#define OFF_QS    0                 // 16*64*4 = 4096
#define OFF_SSUM  4096              // 16*16*4 = 1024
#define OFF_SINV  5120              // 16*4 = 64 (+pad)
#define OFF_STAGE 5376              // K: 4*KBUF u16 (73728B), V: 4*VBUF u16 (69632B)
#define VOFF_U    36864             // u16 offset of V region within stage
#define SMEM_BYTES (5376 + 143360)  // 148736

// global bf16 scratch (pre-converted)
__device__ __align__(16) uint16_t g_khi[64u * 2048u * 64u];
__device__ __align__(16) uint16_t g_klo[64u * 2048u * 64u];
__device__ __align__(16) uint16_t g_vthi[64u * 64u * 2048u];   // [head][d][key]
__device__ __align__(16) uint16_t g_vtlo[64u * 64u * 2048u];

__device__ __forceinline__ void mma16816(float c[4], const uint32_t a[4], const uint32_t b[2]) {
    asm volatile(
        "mma.sync.aligned.m16n8k16.row.col.f32.bf16.bf16.f32 "
        "{%0,%1,%2,%3}, {%4,%5,%6,%7}, {%8,%9}, {%0,%1,%2,%3};\n"
        : "+f"(c[0]), "+f"(c[1]), "+f"(c[2]), "+f"(c[3])
        : "r"(a[0]), "r"(a[1]), "r"(a[2]), "r"(a[3]), "r"(b[0]), "r"(b[1]));
}

__device__ __forceinline__ void mma16808(float c[4], uint32_t a0, uint32_t a1, uint32_t b0) {
    asm volatile(
        "mma.sync.aligned.m16n8k8.row.col.f32.bf16.bf16.f32 "
        "{%0,%1,%2,%3}, {%4,%5}, {%6}, {%0,%1,%2,%3};\n"
        : "+f"(c[0]), "+f"(c[1]), "+f"(c[2]), "+f"(c[3])
        : "r"(a0), "r"(a1), "r"(b0));
}

__device__ __forceinline__ void split2(float x, float y, uint32_t &hi, uint32_t &lo) {
    __nv_bfloat16 hx = __float2bfloat16(x);
    __nv_bfloat16 hy = __float2bfloat16(y);
    float rx = x - __bfloat162float(hx);
    float ry = y - __bfloat162float(hy);
    hi = ((uint32_t)__bfloat16_as_ushort(hy) << 16) | (uint32_t)__bfloat16_as_ushort(hx);
    lo = ((uint32_t)__bfloat16_as_ushort(__float2bfloat16(ry)) << 16) |
          (uint32_t)__bfloat16_as_ushort(__float2bfloat16(rx));
}

__device__ __forceinline__ void split1(float x, uint16_t &h, uint16_t &l) {
    __nv_bfloat16 hx = __float2bfloat16(x);
    h = __bfloat16_as_ushort(hx);
    l = __bfloat16_as_ushort(__float2bfloat16(x - __bfloat162float(hx)));
}

__device__ __forceinline__ uint32_t s2u(const void* p) {
    return (uint32_t)__cvta_generic_to_shared(p);
}
__device__ __forceinline__ void cpa16(uint32_t dst, const void* src) {
    asm volatile("cp.async.cg.shared.global [%0], [%1], 16;\n" :: "r"(dst), "l"(src));
}
#define CP_COMMIT() asm volatile("cp.async.commit_group;\n" ::: "memory")
#define CP_WAIT1()  asm volatile("cp.async.wait_group 1;\n" ::: "memory")
#define CP_WAIT0()  asm volatile("cp.async.wait_group 0;\n" ::: "memory")

// ---------------- pre-convert kernels ----------------
__global__ void conv_k_kernel(const float* __restrict__ kg) {
    int idx = blockIdx.x * blockDim.x + threadIdx.x;
    float4 v = ((const float4*)kg)[idx];
    uint32_t h0, l0, h1, l1;
    split2(v.x, v.y, h0, l0);
    split2(v.z, v.w, h1, l1);
    *(uint2*)(g_khi + (size_t)idx * 4) = make_uint2(h0, h1);
    *(uint2*)(g_klo + (size_t)idx * 4) = make_uint2(l0, l1);
}

__global__ void conv_vt_kernel(const float* __restrict__ vg) {
    __shared__ uint16_t th[64 * KSTR];
    __shared__ uint16_t tl[64 * KSTR];
    const int head = blockIdx.y;
    const int kt   = blockIdx.x;
    const int tid  = threadIdx.x;
    const float* src = vg + (size_t)head * SDIM * DDIM + (size_t)kt * 64 * DDIM;
    #pragma unroll
    for (int rep = 0; rep < 4; ++rep) {
        int lin = tid + rep * 256;
        int key = lin >> 4, d4 = (lin & 15) * 4;
        float4 v = ((const float4*)src)[lin];
        uint16_t h, l;
        split1(v.x, h, l); th[(d4 + 0) * KSTR + key] = h; tl[(d4 + 0) * KSTR + key] = l;
        split1(v.y, h, l); th[(d4 + 1) * KSTR + key] = h; tl[(d4 + 1) * KSTR + key] = l;
        split1(v.z, h, l); th[(d4 + 2) * KSTR + key] = h; tl[(d4 + 2) * KSTR + key] = l;
        split1(v.w, h, l); th[(d4 + 3) * KSTR + key] = h; tl[(d4 + 3) * KSTR + key] = l;
    }
    __syncthreads();
    uint16_t* dsth = g_vthi + (size_t)head * 64 * SDIM + (size_t)kt * 64;
    uint16_t* dstl = g_vtlo + (size_t)head * 64 * SDIM + (size_t)kt * 64;
    #pragma unroll
    for (int rep = 0; rep < 2; ++rep) {
        int lin = tid + rep * 256;
        int row = lin >> 3, c = (lin & 7) * 8;
        *(uint4*)(dsth + (size_t)row * SDIM + c) = *(uint4*)(th + row * KSTR + c);
        *(uint4*)(dstl + (size_t)row * SDIM + c) = *(uint4*)(tl + row * KSTR + c);
    }
}

// ---------------- main fused kernel (register-resident P) ----------------
__global__ __launch_bounds__(NTHREADS, 1)
void attn_mma_kernel(const float* __restrict__ qg, float* __restrict__ outg,
                     float* __restrict__ attng)
{
    extern __shared__ char smraw[];
    float*    qs   = (float*)(smraw + OFF_QS);
    float*    ssum = (float*)(smraw + OFF_SSUM);
    float*    sinv = (float*)(smraw + OFF_SINV);
    uint16_t* stg  = (uint16_t*)(smraw + OFF_STAGE);

    const int bh    = blockIdx.y;
    const int qbase = blockIdx.x * TQ;
    const int tid   = threadIdx.x;
    const int lane  = tid & 31;
    const int wid   = tid >> 5;

    const size_t headoff = (size_t)bh * SDIM * DDIM;
    const uint16_t* khi = g_khi + headoff;
    const uint16_t* klo = g_klo + headoff;
    const uint16_t* vth = g_vthi + headoff;
    const uint16_t* vtl = g_vtlo + headoff;

    for (int idx = tid; idx < TQ * DDIM; idx += NTHREADS)
        qs[idx] = qg[headoff + (size_t)qbase * DDIM + idx] * 0.125f;
    __syncthreads();

    const int r4 = lane >> 2;
    const int c0 = (lane & 3) * 2;
    const int nChunks = (qbase + TQ + CHUNK - 1) >> 7;
    const int cend = nChunks << 7;

    // Q A-fragments (persist both passes)
    uint32_t aqh[4][4], aql[4][4];
    #pragma unroll
    for (int ks = 0; ks < 4; ++ks) {
        const float* q0 = qs + r4 * DDIM + ks * 16;
        const float* q1 = qs + (r4 + 8) * DDIM + ks * 16;
        split2(q0[c0],     q0[c0 + 1], aqh[ks][0], aql[ks][0]);
        split2(q1[c0],     q1[c0 + 1], aqh[ks][1], aql[ks][1]);
        split2(q0[c0 + 8], q0[c0 + 9], aqh[ks][2], aql[ks][2]);
        split2(q1[c0 + 8], q1[c0 + 9], aqh[ks][3], aql[ks][3]);
    }

    auto stageK = [&](int buf, int cidx) {
        uint16_t* hi = stg + buf * 2 * KBUF;
        uint16_t* lo = hi + KBUF;
        const int jb = cidx << 7;
        #pragma unroll
        for (int rep = 0; rep < 2; ++rep) {
            int lin = tid + rep * NTHREADS;      // 1024: 128 keys x 8 (16B units)
            int key = lin >> 3, c16 = (lin & 7) * 8;
            cpa16(s2u(hi + key * KSTR + c16), khi + (size_t)(jb + key) * DDIM + c16);
            cpa16(s2u(lo + key * KSTR + c16), klo + (size_t)(jb + key) * DDIM + c16);
        }
    };
    auto stageV = [&](int buf, int cidx) {
        uint16_t* hi = stg + VOFF_U + buf * 2 * VBUF;
        uint16_t* lo = hi + VBUF;
        const int jb = cidx << 7;
        #pragma unroll
        for (int rep = 0; rep < 2; ++rep) {
            int lin = tid + rep * NTHREADS;      // 1024: 64 rows x 16 (16B units)
            int row = lin >> 4, c16 = (lin & 15) * 8;
            cpa16(s2u(hi + row * VSTR + c16), vth + (size_t)row * SDIM + jb + c16);
            cpa16(s2u(lo + row * VSTR + c16), vtl + (size_t)row * SDIM + jb + c16);
        }
    };

    const int keyb  = (wid << 3) + (lane >> 2);   // key (within chunk) this thread's B covers
    const int row0  = qbase + r4;
    const int row1  = qbase + r4 + 8;

    // QK for one chunk from staged buffer -> acc[4]
    auto qkChunk = [&](int buf, float acc[4]) {
        const uint16_t* hib = stg + buf * 2 * KBUF;
        const uint16_t* lob = hib + KBUF;
        acc[0] = acc[1] = acc[2] = acc[3] = 0.f;
        #pragma unroll
        for (int ks = 0; ks < 4; ++ks) {
            const int d0 = ks * 16 + c0;
            uint32_t bh2[2], bl2[2];
            bh2[0] = *(const uint32_t*)(hib + keyb * KSTR + d0);
            bh2[1] = *(const uint32_t*)(hib + keyb * KSTR + d0 + 8);
            bl2[0] = *(const uint32_t*)(lob + keyb * KSTR + d0);
            bl2[1] = *(const uint32_t*)(lob + keyb * KSTR + d0 + 8);
            mma16816(acc, aqh[ks], bh2);
            mma16816(acc, aql[ks], bh2);
            mma16816(acc, aqh[ks], bl2);
        }
    };

    // ================= PASS 1: row sums of exp(scores) =================
    float s0 = 0.f, s1 = 0.f;
    stageK(0, 0);
    CP_COMMIT();
    for (int c = 0; c < nChunks; ++c) {
        int cn = c + 1 < nChunks ? c + 1 : nChunks - 1;
        stageK((c + 1) & 1, cn);
        CP_COMMIT();
        CP_WAIT1();
        __syncthreads();

        float acc[4];
        qkChunk(c & 1, acc);

        const int col = (c << 7) + (wid << 3) + c0;   // this thread's first col
        // causal: col valid iff col <= row
        s0 += (col     <= row0) ? __expf(acc[0]) : 0.f;
        s0 += (col + 1 <= row0) ? __expf(acc[1]) : 0.f;
        s1 += (col     <= row1) ? __expf(acc[2]) : 0.f;
        s1 += (col + 1 <= row1) ? __expf(acc[3]) : 0.f;
        __syncthreads();
    }
    CP_WAIT0();
    __syncthreads();

    // reduce sums: over the 4-lane c0 group, then across 16 warps via smem
    s0 += __shfl_xor_sync(0xffffffffu, s0, 1);
    s0 += __shfl_xor_sync(0xffffffffu, s0, 2);
    s1 += __shfl_xor_sync(0xffffffffu, s1, 1);
    s1 += __shfl_xor_sync(0xffffffffu, s1, 2);
    if ((lane & 3) == 0) {
        ssum[r4 * 16 + wid]       = s0;
        ssum[(r4 + 8) * 16 + wid] = s1;
    }
    __syncthreads();
    if (tid < TQ) {
        float s = 0.f;
        #pragma unroll
        for (int w = 0; w < 16; ++w) s += ssum[tid * 16 + w];
        sinv[tid] = 1.0f / s;
    }
    __syncthreads();

    const float invs0 = sinv[r4];
    const float invs1 = sinv[r4 + 8];

    // ================= PASS 2: recompute QK, write attn, PV =================
    float oc[8][4];
    #pragma unroll
    for (int nt = 0; nt < 8; ++nt)
        oc[nt][0] = oc[nt][1] = oc[nt][2] = oc[nt][3] = 0.f;

    stageK(0, 0);
    stageV(0, 0);
    CP_COMMIT();
    for (int c = 0; c < nChunks; ++c) {
        int cn = c + 1 < nChunks ? c + 1 : nChunks - 1;
        stageK((c + 1) & 1, cn);
        stageV((c + 1) & 1, cn);
        CP_COMMIT();
        CP_WAIT1();
        __syncthreads();

        float acc[4];
        qkChunk(c & 1, acc);

        const int col = (c << 7) + (wid << 3) + c0;
        float p0 = (col     <= row0) ? __expf(acc[0]) : 0.f;
        float p1 = (col + 1 <= row0) ? __expf(acc[1]) : 0.f;
        float p2 = (col     <= row1) ? __expf(acc[2]) : 0.f;
        float p3 = (col + 1 <= row1) ? __expf(acc[3]) : 0.f;

        if (attng) {
            float* a0 = attng + ((size_t)bh * SDIM + row0) * SDIM + col;
            float* a1 = attng + ((size_t)bh * SDIM + row1) * SDIM + col;
            *(float2*)a0 = make_float2(p0 * invs0, p1 * invs0);
            *(float2*)a1 = make_float2(p2 * invs1, p3 * invs1);
        }

        // pack P into m16n8k8 A-fragments (hi/lo)
        uint32_t ah0, al0, ah1, al1;
        split2(p0, p1, ah0, al0);
        split2(p2, p3, ah1, al1);

        // PV over this warp's 8 keys: 8 n-tiles covering d=0..63
        const uint16_t* vhib = stg + VOFF_U + (c & 1) * 2 * VBUF;
        const uint16_t* vlob = vhib + VBUF;
        const int kl = (wid << 3) + c0;          // key pair base within chunk
        #pragma unroll
        for (int nt = 0; nt < 8; ++nt) {
            const int d = nt * 8 + (lane >> 2);
            uint32_t bhv = *(const uint32_t*)(vhib + d * VSTR + kl);
            uint32_t blv = *(const uint32_t*)(vlob + d * VSTR + kl);
            mma16808(oc[nt], ah0, ah1, bhv);
            mma16808(oc[nt], al0, al1, bhv);
            mma16808(oc[nt], ah0, ah1, blv);
        }
        __syncthreads();
    }
    CP_WAIT0();
    __syncthreads();

    // zero attn tail cols [cend, 2048)
    if (attng) {
        const int j = cend + tid * 4;
        if (j < SDIM) {
            #pragma unroll 1
            for (int r = 0; r < TQ; ++r)
                *(float4*)(attng + ((size_t)bh * SDIM + qbase + r) * SDIM + j) =
                    make_float4(0.f, 0.f, 0.f, 0.f);
        }
    }

    // ---- cross-warp PV reduction via smem (reuse staging area) ----
    float* red = (float*)(smraw + OFF_STAGE);    // [16 warps][16 rows][64 d]
    {
        float* base = red + wid * 1024;
        #pragma unroll
        for (int nt = 0; nt < 8; ++nt) {
            const int d = nt * 8 + c0;
            *(float2*)(base + r4 * 64 + d)       = make_float2(oc[nt][0], oc[nt][1]);
            *(float2*)(base + (r4 + 8) * 64 + d) = make_float2(oc[nt][2], oc[nt][3]);
        }
    }
    __syncthreads();
    {
        const int e = tid * 2;                   // element pair: row = e/64, d = e%64
        const int row = e >> 6;
        const int d   = e & 63;
        float a = 0.f, b = 0.f;
        #pragma unroll
        for (int w = 0; w < 16; ++w) {
            float2 v = *(const float2*)(red + w * 1024 + e);
            a += v.x; b += v.y;
        }
        const float sc = sinv[row];
        float* orow = outg + headoff + (size_t)(qbase + row) * DDIM + d;
        *(float2*)orow = make_float2(a * sc, b * sc);
    }
}

extern "C" void kernel_launch(void* const* d_in, const int* in_sizes, int n_in,
                              void* d_out, int out_size) {
    const float* q = (const float*)d_in[0];
    const float* k = (const float*)d_in[1];
    const float* v = (const float*)d_in[2];

    float* out = (float*)d_out;
    const long long OUT_E  = 64LL * 2048 * 64;
    const long long ATTN_E = 64LL * 2048 * 2048;
    float* attn = ((long long)out_size >= OUT_E + ATTN_E) ? out + OUT_E : nullptr;

    conv_k_kernel<<<8192, 256>>>(k);
    {
        dim3 g(32, 64);
        conv_vt_kernel<<<g, 256>>>(v);
    }

    cudaFuncSetAttribute(attn_mma_kernel,
                         cudaFuncAttributeMaxDynamicSharedMemorySize, SMEM_BYTES);
    dim3 grid(SDIM / TQ, 64);
    attn_mma_kernel<<<grid, NTHREADS, SMEM_BYTES>>>(q, out, attn);
}

// round 5
// speedup vs baseline: 1.9873x; 1.9873x over previous
#include <cuda_runtime.h>
#include <cuda_fp16.h>
#include <cuda_bf16.h>
#include <stdint.h>

#define SDIM 2048
#define DDIM 64
#define TQ 32
#define CHUNK 64
#define NTHREADS 512
#define SCH 2088            // sc row stride (u16): bank-conflict-free packed stores

// smem byte offsets
#define OFF_SC    0                  // 32*2088*2 = 133632
#define OFF_QS    133632             // 32*64*4   = 8192
#define OFF_KB    141824             // 2 bufs * 4096 u32 = 32768
#define OFF_VB    174592             // 32768
#define OFF_SSUM  207360             // 32*8*4 = 1024
#define OFF_SINV  208384             // 128
#define OFF_MBAR  208512             // 2 mbarriers
#define SMEM_BYTES 208576

// pre-converted, chunk-blocked, swizzled images: [head][chunk 32][part hi/lo][2048 u32]
__device__ __align__(16) uint32_t g_k[64u * 32u * 2u * 2048u];
__device__ __align__(16) uint32_t g_v[64u * 32u * 2u * 2048u];

__device__ __forceinline__ void mma16816(float c[4], const uint32_t a[4], const uint32_t b[2]) {
    asm volatile(
        "mma.sync.aligned.m16n8k16.row.col.f32.bf16.bf16.f32 "
        "{%0,%1,%2,%3}, {%4,%5,%6,%7}, {%8,%9}, {%0,%1,%2,%3};\n"
        : "+f"(c[0]), "+f"(c[1]), "+f"(c[2]), "+f"(c[3])
        : "r"(a[0]), "r"(a[1]), "r"(a[2]), "r"(a[3]), "r"(b[0]), "r"(b[1]));
}
__device__ __forceinline__ void mma16808(float c[4], uint32_t a0, uint32_t a1, uint32_t b0) {
    asm volatile(
        "mma.sync.aligned.m16n8k8.row.col.f32.bf16.bf16.f32 "
        "{%0,%1,%2,%3}, {%4,%5}, {%6}, {%0,%1,%2,%3};\n"
        : "+f"(c[0]), "+f"(c[1]), "+f"(c[2]), "+f"(c[3])
        : "r"(a0), "r"(a1), "r"(b0));
}

__device__ __forceinline__ void split2(float x, float y, uint32_t &hi, uint32_t &lo) {
    __nv_bfloat16 hx = __float2bfloat16(x);
    __nv_bfloat16 hy = __float2bfloat16(y);
    float rx = x - __bfloat162float(hx);
    float ry = y - __bfloat162float(hy);
    hi = ((uint32_t)__bfloat16_as_ushort(hy) << 16) | (uint32_t)__bfloat16_as_ushort(hx);
    lo = ((uint32_t)__bfloat16_as_ushort(__float2bfloat16(ry)) << 16) |
          (uint32_t)__bfloat16_as_ushort(__float2bfloat16(rx));
}
__device__ __forceinline__ void split1(float x, uint16_t &h, uint16_t &l) {
    __nv_bfloat16 hx = __float2bfloat16(x);
    h = __bfloat16_as_ushort(hx);
    l = __bfloat16_as_ushort(__float2bfloat16(x - __bfloat162float(hx)));
}

__device__ __forceinline__ uint32_t s2u(const void* p) {
    return (uint32_t)__cvta_generic_to_shared(p);
}
__device__ __forceinline__ void bulk_cp(uint32_t dst, const void* src, uint32_t bytes, uint32_t mbar) {
    asm volatile(
        "cp.async.bulk.shared::cluster.global.mbarrier::complete_tx::bytes [%0], [%1], %2, [%3];"
        :: "r"(dst), "l"(src), "r"(bytes), "r"(mbar) : "memory");
}
#define MBAR_INIT(mb, n) \
    asm volatile("mbarrier.init.shared.b64 [%0], %1;" :: "r"(mb), "r"(n) : "memory")
#define MBAR_EXPECT(mb, tx) \
    asm volatile("mbarrier.arrive.expect_tx.shared.b64 _, [%0], %1;" :: "r"(mb), "r"(tx) : "memory")
__device__ __forceinline__ void mbar_wait(uint32_t mb, uint32_t parity) {
    asm volatile(
        "{\n\t.reg .pred P;\n\t"
        "W_%=:\n\t"
        "mbarrier.try_wait.parity.acquire.cta.shared::cta.b64 P, [%0], %1, 0x989680;\n\t"
        "@P bra.uni D_%=;\n\t"
        "bra.uni W_%=;\n\t"
        "D_%=:\n\t}"
        :: "r"(mb), "r"(parity) : "memory");
}

// ---------------- pre-convert: K -> chunk-blocked swizzled bf16 hi/lo ----------------
// image word (within 8KB part): w = key6*32 + d/2,  w' = w ^ ((key6&7)<<2)
__global__ void conv_k_kernel(const float* __restrict__ kg) {
    int idx = blockIdx.x * blockDim.x + threadIdx.x;   // float4 id
    float4 v = ((const float4*)kg)[idx];
    int kgl = idx >> 4;                // head*2048 + key
    int d4  = (idx & 15) * 4;
    int head = kgl >> 11, key = kgl & 2047;
    int chunk = key >> 6, k6 = key & 63;
    uint32_t h0, l0, h1, l1;
    split2(v.x, v.y, h0, l0);
    split2(v.z, v.w, h1, l1);
    uint32_t wp = (uint32_t)(k6 * 32 + (d4 >> 1)) ^ ((uint32_t)(k6 & 7) << 2);
    size_t base = (size_t)(head * 32 + chunk) * 2 * 2048;
    g_k[base + wp]          = h0;
    g_k[base + wp + 1]      = h1;
    g_k[base + 2048 + wp]     = l0;
    g_k[base + 2048 + wp + 1] = l1;
}

// V -> transposed [d][key] chunk-blocked swizzled: w = d*32 + keypair, w' = w ^ ((d&7)<<2)
__global__ void conv_v_kernel(const float* __restrict__ vg) {
    __shared__ uint16_t th[64 * 68];
    __shared__ uint16_t tl[64 * 68];
    const int head = blockIdx.y, chunk = blockIdx.x, tid = threadIdx.x;
    const float4* src = (const float4*)(vg + ((size_t)head * SDIM + chunk * 64) * DDIM);
    #pragma unroll
    for (int rep = 0; rep < 4; ++rep) {
        int lin = tid + rep * 256;
        int key = lin >> 4, d4 = (lin & 15) * 4;
        float4 v = src[lin];
        uint16_t h, l;
        split1(v.x, h, l); th[(d4 + 0) * 68 + key] = h; tl[(d4 + 0) * 68 + key] = l;
        split1(v.y, h, l); th[(d4 + 1) * 68 + key] = h; tl[(d4 + 1) * 68 + key] = l;
        split1(v.z, h, l); th[(d4 + 2) * 68 + key] = h; tl[(d4 + 2) * 68 + key] = l;
        split1(v.w, h, l); th[(d4 + 3) * 68 + key] = h; tl[(d4 + 3) * 68 + key] = l;
    }
    __syncthreads();
    size_t base = (size_t)(head * 32 + chunk) * 2 * 2048;
    #pragma unroll
    for (int rep = 0; rep < 8; ++rep) {
        int lin = tid + rep * 256;          // 2048 words
        int d = lin >> 5, kp = lin & 31;
        uint32_t hi = (uint32_t)th[d * 68 + kp * 2] | ((uint32_t)th[d * 68 + kp * 2 + 1] << 16);
        uint32_t lo = (uint32_t)tl[d * 68 + kp * 2] | ((uint32_t)tl[d * 68 + kp * 2 + 1] << 16);
        uint32_t wp = (uint32_t)(d * 32) + ((uint32_t)kp ^ ((uint32_t)(d & 7) << 2));
        g_v[base + wp]        = hi;
        g_v[base + 2048 + wp] = lo;
    }
}

// ---------------- fused single-pass attention ----------------
__global__ __launch_bounds__(NTHREADS, 1)
void attn_kernel(const float* __restrict__ qg, float* __restrict__ outg,
                 float* __restrict__ attng)
{
    extern __shared__ char sm[];
    uint16_t* sc   = (uint16_t*)(sm + OFF_SC);     // [32][SCH] fp16 unnormalized p
    float*    qs   = (float*)(sm + OFF_QS);
    uint32_t* kb   = (uint32_t*)(sm + OFF_KB);     // [2][4096] (hi 2048 | lo 2048)
    uint32_t* vbuf = (uint32_t*)(sm + OFF_VB);
    float*    ssum = (float*)(sm + OFF_SSUM);      // [32][8]
    float*    sinv = (float*)(sm + OFF_SINV);

    const int bh = blockIdx.y, qbase = blockIdx.x * TQ;
    const int tid = threadIdx.x, lane = tid & 31, wid = tid >> 5;
    const int w7 = wid & 7, rbase = (wid >= 8) ? 16 : 0;
    const int r4 = lane >> 2, l3 = lane & 3, c0 = l3 * 2;

    const size_t headoff = (size_t)bh * SDIM * DDIM;
    for (int i = tid; i < TQ * DDIM; i += NTHREADS)
        qs[i] = qg[headoff + (size_t)qbase * DDIM + i] * 0.125f;

    const uint32_t mb0 = s2u(sm + OFF_MBAR), mb1 = mb0 + 8;
    if (tid == 0) { MBAR_INIT(mb0, 1); MBAR_INIT(mb1, 1); }
    __syncthreads();

    const int nChunks = (qbase + TQ + CHUNK - 1) / CHUNK;
    const int cend = nChunks * CHUNK;
    const size_t gbase = (size_t)bh * 32 * 2 * 2048;   // u32 index of this head's image

    if (tid == 0) {
        MBAR_EXPECT(mb0, 32768);
        bulk_cp(s2u(kb),   g_k + gbase, 16384, mb0);
        bulk_cp(s2u(vbuf), g_v + gbase, 16384, mb0);
    }

    // Q A-fragments (rows rbase..rbase+15)
    uint32_t aqh[4][4], aql[4][4];
    #pragma unroll
    for (int ks = 0; ks < 4; ++ks) {
        const float* q0 = qs + (rbase + r4) * DDIM + ks * 16;
        const float* q1 = q0 + 8 * DDIM;
        split2(q0[c0],     q0[c0 + 1], aqh[ks][0], aql[ks][0]);
        split2(q1[c0],     q1[c0 + 1], aqh[ks][1], aql[ks][1]);
        split2(q0[c0 + 8], q0[c0 + 9], aqh[ks][2], aql[ks][2]);
        split2(q1[c0 + 8], q1[c0 + 9], aqh[ks][3], aql[ks][3]);
    }

    float oc[8][4];
    #pragma unroll
    for (int nt = 0; nt < 8; ++nt)
        oc[nt][0] = oc[nt][1] = oc[nt][2] = oc[nt][3] = 0.f;
    float s0 = 0.f, s1 = 0.f;

    const int row0 = qbase + rbase + r4, row1 = row0 + 8;
    const uint32_t xm = (uint32_t)(lane >> 2) << 2;   // swizzle XOR (key&7 / d&7 == lane>>2)
    const int kwb = (w7 * 8 + (lane >> 2)) * 32;      // QK key row base (words)
    const int vcol = w7 * 4 + l3;                     // PV key-pair column

    for (int c = 0; c < nChunks; ++c) {
        const int buf = c & 1;
        const uint32_t ph = (uint32_t)((c >> 1) & 1);
        __syncthreads();   // prev users of buf^1 done
        if (tid == 0 && c + 1 < nChunks) {
            const uint32_t mbn = buf ? mb0 : mb1;
            MBAR_EXPECT(mbn, 32768);
            const size_t off = gbase + (size_t)(c + 1) * 4096;
            bulk_cp(s2u(kb + (buf ^ 1) * 4096),   g_k + off, 16384, mbn);
            bulk_cp(s2u(vbuf + (buf ^ 1) * 4096), g_v + off, 16384, mbn);
        }
        mbar_wait(buf ? mb1 : mb0, ph);

        // ---- QK ----
        const uint32_t* kh = kb + buf * 4096;
        const uint32_t* kl = kh + 2048;
        float acc[4] = {0.f, 0.f, 0.f, 0.f};
        #pragma unroll
        for (int ks = 0; ks < 4; ++ks) {
            const uint32_t i0 = kwb + (((uint32_t)(ks * 8 + l3))     ^ xm);
            const uint32_t i1 = kwb + (((uint32_t)(ks * 8 + l3 + 4)) ^ xm);
            uint32_t bh2[2] = {kh[i0], kh[i1]};
            uint32_t bl2[2] = {kl[i0], kl[i1]};
            mma16816(acc, aqh[ks], bh2);
            mma16816(acc, aql[ks], bh2);
            mma16816(acc, aqh[ks], bl2);
        }

        // ---- exp + sums + sc store ----
        const int col = c * CHUNK + w7 * 8 + c0;
        float p0 = (col     <= row0) ? __expf(acc[0]) : 0.f;
        float p1 = (col + 1 <= row0) ? __expf(acc[1]) : 0.f;
        float p2 = (col     <= row1) ? __expf(acc[2]) : 0.f;
        float p3 = (col + 1 <= row1) ? __expf(acc[3]) : 0.f;
        s0 += p0 + p1;
        s1 += p2 + p3;

        __half2 h01 = __floats2half2_rn(p0, p1);
        __half2 h23 = __floats2half2_rn(p2, p3);
        *(uint32_t*)(sc + (rbase + r4) * SCH + col)     = *(uint32_t*)&h01;
        *(uint32_t*)(sc + (rbase + r4 + 8) * SCH + col) = *(uint32_t*)&h23;

        // ---- PV (this warp's 8-key slice, all 64 d) ----
        uint32_t ah0, al0, ah1, al1;
        split2(p0, p1, ah0, al0);
        split2(p2, p3, ah1, al1);
        const uint32_t* vh = vbuf + buf * 4096;
        const uint32_t* vl = vh + 2048;
        #pragma unroll
        for (int nt = 0; nt < 8; ++nt) {
            const int d = nt * 8 + (lane >> 2);
            const uint32_t vi = (uint32_t)(d * 32) + ((uint32_t)vcol ^ xm);
            const uint32_t bhv = vh[vi], blv = vl[vi];
            mma16808(oc[nt], ah0, ah1, bhv);
            mma16808(oc[nt], al0, al1, bhv);
            mma16808(oc[nt], ah0, ah1, blv);
        }
    }

    // ---- row sums -> sinv ----
    s0 += __shfl_xor_sync(0xffffffffu, s0, 1);
    s0 += __shfl_xor_sync(0xffffffffu, s0, 2);
    s1 += __shfl_xor_sync(0xffffffffu, s1, 1);
    s1 += __shfl_xor_sync(0xffffffffu, s1, 2);
    if (l3 == 0) {
        ssum[(rbase + r4) * 8 + w7]     = s0;
        ssum[(rbase + r4 + 8) * 8 + w7] = s1;
    }
    __syncthreads();
    if (tid < TQ) {
        float s = 0.f;
        #pragma unroll
        for (int w = 0; w < 8; ++w) s += ssum[tid * 8 + w];
        sinv[tid] = 1.0f / s;
    }
    __syncthreads();

    // ---- attn write (coalesced float4 rows) ----
    if (attng) {
        const int j = tid * 4;
        #pragma unroll 1
        for (int r = 0; r < TQ; ++r) {
            const float invr = sinv[r];
            float4 o;
            if (j < cend) {
                uint2 pk = *(const uint2*)(sc + r * SCH + j);
                float2 fa = __half22float2(*(__half2*)&pk.x);
                float2 fb = __half22float2(*(__half2*)&pk.y);
                o = make_float4(fa.x * invr, fa.y * invr, fb.x * invr, fb.y * invr);
            } else {
                o = make_float4(0.f, 0.f, 0.f, 0.f);
            }
            *(float4*)(attng + ((size_t)bh * SDIM + qbase + r) * SDIM + j) = o;
        }
    }

    // ---- PV cross-warp reduction (reuse staging smem) ----
    float* red = (float*)(sm + OFF_KB);   // [16 warps][16 rows][64 d]
    {
        float* wb = red + wid * 1024;
        #pragma unroll
        for (int nt = 0; nt < 8; ++nt) {
            const int d = nt * 8 + c0;
            *(float2*)(wb + r4 * 64 + d)       = make_float2(oc[nt][0], oc[nt][1]);
            *(float2*)(wb + (r4 + 8) * 64 + d) = make_float2(oc[nt][2], oc[nt][3]);
        }
    }
    __syncthreads();
    {
        const int L = tid * 4;            // 32 rows x 64 d / 512 threads
        const int row = L >> 6, d = L & 63;
        const int wb = (row >> 4) * 8;
        float4 a = make_float4(0.f, 0.f, 0.f, 0.f);
        #pragma unroll
        for (int w = 0; w < 8; ++w) {
            float4 t = *(const float4*)(red + (wb + w) * 1024 + (row & 15) * 64 + d);
            a.x += t.x; a.y += t.y; a.z += t.z; a.w += t.w;
        }
        const float sv = sinv[row];
        *(float4*)(outg + headoff + (size_t)(qbase + row) * DDIM + d) =
            make_float4(a.x * sv, a.y * sv, a.z * sv, a.w * sv);
    }
}

extern "C" void kernel_launch(void* const* d_in, const int* in_sizes, int n_in,
                              void* d_out, int out_size) {
    const float* q = (const float*)d_in[0];
    const float* k = (const float*)d_in[1];
    const float* v = (const float*)d_in[2];

    float* out = (float*)d_out;
    const long long OUT_E  = 64LL * 2048 * 64;
    const long long ATTN_E = 64LL * 2048 * 2048;
    float* attn = ((long long)out_size >= OUT_E + ATTN_E) ? out + OUT_E : nullptr;

    conv_k_kernel<<<8192, 256>>>(k);
    {
        dim3 g(32, 64);
        conv_v_kernel<<<g, 256>>>(v);
    }

    cudaFuncSetAttribute(attn_kernel,
                         cudaFuncAttributeMaxDynamicSharedMemorySize, SMEM_BYTES);
    dim3 grid(SDIM / TQ, 64);
    attn_kernel<<<grid, NTHREADS, SMEM_BYTES>>>(q, out, attn);
}